// round 4
// baseline (speedup 1.0000x reference)
#include <cuda_runtime.h>
#include <cstdint>

#define NFEAT 256
#define NHID 64
#define NEG_SLOPE 0.05f
#define MAX_N 100000
#define MAX_E 1600000
#define BM 128
#define BK 32

// ---------------- device scratch (no allocation allowed) ----------------
__device__ float g_Wh[(size_t)MAX_N * NHID];   // 25.6 MB
__device__ float g_si[MAX_N];
__device__ float g_sj[MAX_N];
__device__ float g_hsum[MAX_N];                // later holds reciprocal
__device__ float g_h[MAX_E];                   // 6.4 MB
__device__ int   g_idx64;                      // 1 if edge_index is int64

// ---------------- index helper: dtype-adaptive, clamped ----------------
__device__ __forceinline__ int load_idx(const void* ei, size_t pos, int is64, int M) {
    int v;
    if (is64) v = (int)((const long long*)ei)[pos];
    else      v = ((const int*)ei)[pos];
    v = v < 0 ? 0 : (v >= M ? M - 1 : v);
    return v;
}

// ---------------- kernel -1: detect edge_index dtype ----------------
__global__ void detect_kernel(const void* ei, int E, int M) {
    __shared__ int bad;
    if (threadIdx.x == 0) bad = 0;
    __syncthreads();
    const long long* p = (const long long*)ei;
    int stride = E / 4096 > 0 ? E / 4096 : 1;
    for (int i = threadIdx.x; i < 4096; i += blockDim.x) {
        size_t pos = (size_t)i * stride;
        if (pos < (size_t)E) {
            long long v = p[pos];
            if (v < 0 || v >= M) atomicOr(&bad, 1);
        }
    }
    __syncthreads();
    if (threadIdx.x == 0) g_idx64 = bad ? 0 : 1;
}

// ---------------- kernel 0: zero out-region + h_sum ----------------
__global__ void zero_kernel(float4* __restrict__ out, int M) {
    int i = blockIdx.x * blockDim.x + threadIdx.x;
    if (i < M * (NHID / 4)) out[i] = make_float4(0.f, 0.f, 0.f, 0.f);
    if (i < M) g_hsum[i] = 0.f;
}

// ---------------- kernel 1: Wh = x @ W_fc via packed fp32 (FFMA2) -------
// BM=128, BN=64(full), BK=32, 256 threads, 8x4 micro-tile per thread.
// B stored duplicated ((b,b) pairs) with XOR swizzle -> LDS.64 splat pairs,
// conflict-free. A pairs come free from float4 loads (adjacent rows).
// Score (si,sj) fused into epilogue via half-warp shfl reduction.
__global__ void __launch_bounds__(256) gemm_kernel(
        const float* __restrict__ x,
        const float* __restrict__ W,
        const float* __restrict__ aw,
        int M) {
    __shared__ float As[BK][BM];       // [k][m] transposed, 16KB
    __shared__ float Bs2[BK][128];     // duplicated+swizzled, 16KB

    const int tid = threadIdx.x;
    const int tx  = tid & 15;          // 0..15 -> 4 cols each
    const int ty  = tid >> 4;          // 0..15 -> 8 rows each
    const int g   = (tx >> 2) & 3;     // swizzle group
    const int m0  = blockIdx.x * BM;

    unsigned long long acc2[4][4];     // [m-pair][c], each = (row2i, row2i+1)
#pragma unroll
    for (int i = 0; i < 4; i++)
#pragma unroll
        for (int c = 0; c < 4; c++) acc2[i][c] = 0ULL;

    for (int k0 = 0; k0 < NFEAT; k0 += BK) {
        // load A tile: 128 rows x 32 k, transposed; 4 float4 per thread
#pragma unroll
        for (int p = 0; p < 4; p++) {
            int idx = p * 256 + tid;
            int row = idx >> 3;            // 0..127
            int kc  = (idx & 7) * 4;       // 0,4,...,28
            float4 v = make_float4(0.f, 0.f, 0.f, 0.f);
            int gm = m0 + row;
            if (gm < M) v = *(const float4*)&x[(size_t)gm * NFEAT + k0 + kc];
            As[kc + 0][row] = v.x;
            As[kc + 1][row] = v.y;
            As[kc + 2][row] = v.z;
            As[kc + 3][row] = v.w;
        }
        // load B tile duplicated: value j at swizzled col, stored twice
#pragma unroll
        for (int p = 0; p < 8; p++) {
            int idx = p * 256 + tid;
            int k = idx >> 6;              // 0..31
            int j = idx & 63;
            float v = W[(size_t)(k0 + k) * NHID + j];
            int col = ((j >> 2) << 3) + ((((j & 3) ^ ((j >> 4) & 3))) << 1);
            Bs2[k][col]     = v;
            Bs2[k][col + 1] = v;
        }
        __syncthreads();

#pragma unroll
        for (int k = 0; k < BK; k++) {
            ulonglong2 aL = *(const ulonglong2*)&As[k][ty * 8];
            ulonglong2 aH = *(const ulonglong2*)&As[k][ty * 8 + 4];
            unsigned long long ap[4] = {aL.x, aL.y, aH.x, aH.y};
            unsigned long long bp[4];
#pragma unroll
            for (int c = 0; c < 4; c++)
                bp[c] = *(const unsigned long long*)&Bs2[k][tx * 8 + ((c ^ g) << 1)];
#pragma unroll
            for (int i = 0; i < 4; i++)
#pragma unroll
                for (int c = 0; c < 4; c++)
                    asm("fma.rn.f32x2 %0, %1, %2, %0;"
                        : "+l"(acc2[i][c]) : "l"(ap[i]), "l"(bp[c]));
        }
        __syncthreads();
    }

    // epilogue: store Wh rows + fused score reduction
    float awi[4], awj[4];
#pragma unroll
    for (int c = 0; c < 4; c++) {
        awi[c] = __ldg(&aw[tx * 4 + c]);
        awj[c] = __ldg(&aw[64 + tx * 4 + c]);
    }
#pragma unroll
    for (int i = 0; i < 4; i++) {
        int rowL = m0 + ty * 8 + i * 2;
        int rowH = rowL + 1;
        float lo[4], hi[4];
#pragma unroll
        for (int c = 0; c < 4; c++) {
            lo[c] = __uint_as_float((unsigned)(acc2[i][c] & 0xffffffffULL));
            hi[c] = __uint_as_float((unsigned)(acc2[i][c] >> 32));
        }
        if (rowL < M)
            *(float4*)&g_Wh[(size_t)rowL * NHID + tx * 4] =
                make_float4(lo[0], lo[1], lo[2], lo[3]);
        if (rowH < M)
            *(float4*)&g_Wh[(size_t)rowH * NHID + tx * 4] =
                make_float4(hi[0], hi[1], hi[2], hi[3]);
        // partial scores over this thread's 4 cols
        float siL = 0.f, sjL = 0.f, siH = 0.f, sjH = 0.f;
#pragma unroll
        for (int c = 0; c < 4; c++) {
            siL += lo[c] * awi[c];  sjL += lo[c] * awj[c];
            siH += hi[c] * awi[c];  sjH += hi[c] * awj[c];
        }
        // reduce over tx (lane = (ty&1)*16 + tx, xor 1/2/4/8 stays in half-warp)
#pragma unroll
        for (int o = 8; o >= 1; o >>= 1) {
            siL += __shfl_xor_sync(0xffffffffu, siL, o);
            sjL += __shfl_xor_sync(0xffffffffu, sjL, o);
            siH += __shfl_xor_sync(0xffffffffu, siH, o);
            sjH += __shfl_xor_sync(0xffffffffu, sjH, o);
        }
        if (tx == 0) {
            if (rowL < M) { g_si[rowL] = siL; g_sj[rowL] = sjL; }
            if (rowH < M) { g_si[rowH] = siH; g_sj[rowH] = sjH; }
        }
    }
}

// ---------------- kernel 3: edge pass A: h + hsum scatter ----------------
__global__ void edgeA_kernel(const void* __restrict__ ei,
                             const float* __restrict__ ab, int E, int M) {
    int e = blockIdx.x * blockDim.x + threadIdx.x;
    if (e >= E) return;
    const int is64 = g_idx64;
    int s = load_idx(ei, e, is64, M);
    int d = load_idx(ei, (size_t)E + e, is64, M);
    float sc = g_si[s] + g_sj[d] + __ldg(&ab[0]);
    float l  = sc > 0.f ? sc : NEG_SLOPE * sc;
    float h  = expf(l);
    g_h[e] = h;
    atomicAdd(&g_hsum[s], h);
}

// ---------------- kernel 3.5: reciprocal of h_sum ----------------
__global__ void recip_kernel(int M) {
    int n = blockIdx.x * blockDim.x + threadIdx.x;
    if (n >= M) return;
    g_hsum[n] = __frcp_rn(g_hsum[n]);
}

// ---------------- kernel 4: edge pass B: alpha + weighted scatter --------
__global__ void edgeB_kernel(const void* __restrict__ ei,
                             float* __restrict__ out,
                             float* __restrict__ alpha_out, int E, int M) {
    long long gt = (long long)blockIdx.x * blockDim.x + threadIdx.x;
    int e    = (int)(gt >> 4);
    int part = (int)(gt & 15);
    if (e >= E) return;
    const int is64 = g_idx64;
    int s = load_idx(ei, e, is64, M);
    int d = load_idx(ei, (size_t)E + e, is64, M);
    float alpha = g_h[e] * g_hsum[s];        // hsum holds reciprocal
    if (part == 0 && alpha_out) alpha_out[e] = alpha;
    float4 w = *(const float4*)&g_Wh[(size_t)d * NHID + part * 4];
    float* dst = &out[(size_t)s * NHID + part * 4];
    asm volatile("red.global.add.v4.f32 [%0], {%1,%2,%3,%4};"
                 :: "l"(dst),
                    "f"(w.x * alpha), "f"(w.y * alpha),
                    "f"(w.z * alpha), "f"(w.w * alpha)
                 : "memory");
}

// ---------------- launch ----------------
extern "C" void kernel_launch(void* const* d_in, const int* in_sizes, int n_in,
                              void* d_out, int out_size) {
    const float* x  = (const float*)d_in[0];
    const float* W  = (const float*)d_in[1];
    const float* aw = (const float*)d_in[2];
    const float* ab = (const float*)d_in[3];
    const void*  ei = d_in[4];

    const int M = in_sizes[0] / NFEAT;       // 100000
    const int E = in_sizes[4] / 2;           // 1600000

    float* out       = (float*)d_out;                    // [M, 64]
    float* alpha_out = (out_size >= M * NHID + E) ? out + (size_t)M * NHID : nullptr;

    detect_kernel<<<1, 256>>>(ei, E, M);
    {
        int total = M * (NHID / 4);
        zero_kernel<<<(total + 255) / 256, 256>>>((float4*)out, M);
    }
    gemm_kernel<<<(M + BM - 1) / BM, 256>>>(x, W, aw, M);
    edgeA_kernel<<<(E + 255) / 256, 256>>>(ei, ab, E, M);
    recip_kernel<<<(M + 255) / 256, 256>>>(M);
    {
        long long total = (long long)E * 16;
        edgeB_kernel<<<(int)((total + 255) / 256), 256>>>(ei, out, alpha_out, E, M);
    }
}

// round 6
// speedup vs baseline: 1.0084x; 1.0084x over previous
#include <cuda_runtime.h>
#include <cstdint>

#define NFEAT 256
#define NHID 64
#define NEG_SLOPE 0.05f
#define MAX_N 100000
#define MAX_E 1600000
#define BM 128
#define BK 32

// ---------------- device scratch (no allocation allowed) ----------------
__device__ float g_Wh[(size_t)MAX_N * NHID];   // 25.6 MB
__device__ float g_si[MAX_N];
__device__ float g_sj[MAX_N];
__device__ float g_hsum[MAX_N];                // later holds reciprocal
__device__ int   g_idx64;                      // 1 if edge_index is int64
// CSR build
__device__ int   g_count[MAX_N];
__device__ int   g_start[MAX_N + 1];
__device__ int   g_cursor[MAX_N];
__device__ int   g_bsum[512];
__device__ int   g_boff[512];
__device__ int   g_perm[MAX_E];                // sorted pos -> original edge id
__device__ int   g_dsts[MAX_E];                // dst in sorted order
__device__ float g_hs[MAX_E];                  // h in sorted order

// ---------------- index helper: dtype-adaptive, clamped ----------------
__device__ __forceinline__ int load_idx(const void* ei, size_t pos, int is64, int M) {
    int v;
    if (is64) v = (int)((const long long*)ei)[pos];
    else      v = ((const int*)ei)[pos];
    v = v < 0 ? 0 : (v >= M ? M - 1 : v);
    return v;
}

// ---------------- detect edge_index dtype ----------------
__global__ void detect_kernel(const void* ei, int E, int M) {
    __shared__ int bad;
    if (threadIdx.x == 0) bad = 0;
    __syncthreads();
    const long long* p = (const long long*)ei;
    int stride = E / 4096 > 0 ? E / 4096 : 1;
    for (int i = threadIdx.x; i < 4096; i += blockDim.x) {
        size_t pos = (size_t)i * stride;
        if (pos < (size_t)E) {
            long long v = p[pos];
            if (v < 0 || v >= M) atomicOr(&bad, 1);
        }
    }
    __syncthreads();
    if (threadIdx.x == 0) g_idx64 = bad ? 0 : 1;
}

// ---------------- zero small per-node arrays ----------------
__global__ void zero_small_kernel(int M) {
    int i = blockIdx.x * blockDim.x + threadIdx.x;
    if (i < M) { g_hsum[i] = 0.f; g_count[i] = 0; }
}

// ---------------- GEMM: Wh = x @ W_fc (FFMA2) + fused score ----------------
__global__ void __launch_bounds__(256) gemm_kernel(
        const float* __restrict__ x,
        const float* __restrict__ W,
        const float* __restrict__ aw,
        int M) {
    __shared__ float As[BK][BM];
    __shared__ float Bs2[BK][128];

    const int tid = threadIdx.x;
    const int tx  = tid & 15;
    const int ty  = tid >> 4;
    const int g   = (tx >> 2) & 3;
    const int m0  = blockIdx.x * BM;

    unsigned long long acc2[4][4];
#pragma unroll
    for (int i = 0; i < 4; i++)
#pragma unroll
        for (int c = 0; c < 4; c++) acc2[i][c] = 0ULL;

    for (int k0 = 0; k0 < NFEAT; k0 += BK) {
#pragma unroll
        for (int p = 0; p < 4; p++) {
            int idx = p * 256 + tid;
            int row = idx >> 3;
            int kc  = (idx & 7) * 4;
            float4 v = make_float4(0.f, 0.f, 0.f, 0.f);
            int gm = m0 + row;
            if (gm < M) v = *(const float4*)&x[(size_t)gm * NFEAT + k0 + kc];
            As[kc + 0][row] = v.x;
            As[kc + 1][row] = v.y;
            As[kc + 2][row] = v.z;
            As[kc + 3][row] = v.w;
        }
#pragma unroll
        for (int p = 0; p < 8; p++) {
            int idx = p * 256 + tid;
            int k = idx >> 6;
            int j = idx & 63;
            float v = W[(size_t)(k0 + k) * NHID + j];
            int col = ((j >> 2) << 3) + ((((j & 3) ^ ((j >> 4) & 3))) << 1);
            Bs2[k][col]     = v;
            Bs2[k][col + 1] = v;
        }
        __syncthreads();

#pragma unroll
        for (int k = 0; k < BK; k++) {
            ulonglong2 aL = *(const ulonglong2*)&As[k][ty * 8];
            ulonglong2 aH = *(const ulonglong2*)&As[k][ty * 8 + 4];
            unsigned long long ap[4] = {aL.x, aL.y, aH.x, aH.y};
            unsigned long long bp[4];
#pragma unroll
            for (int c = 0; c < 4; c++)
                bp[c] = *(const unsigned long long*)&Bs2[k][tx * 8 + ((c ^ g) << 1)];
#pragma unroll
            for (int i = 0; i < 4; i++)
#pragma unroll
                for (int c = 0; c < 4; c++)
                    asm("fma.rn.f32x2 %0, %1, %2, %0;"
                        : "+l"(acc2[i][c]) : "l"(ap[i]), "l"(bp[c]));
        }
        __syncthreads();
    }

    float awi[4], awj[4];
#pragma unroll
    for (int c = 0; c < 4; c++) {
        awi[c] = __ldg(&aw[tx * 4 + c]);
        awj[c] = __ldg(&aw[64 + tx * 4 + c]);
    }
#pragma unroll
    for (int i = 0; i < 4; i++) {
        int rowL = m0 + ty * 8 + i * 2;
        int rowH = rowL + 1;
        float lo[4], hi[4];
#pragma unroll
        for (int c = 0; c < 4; c++) {
            lo[c] = __uint_as_float((unsigned)(acc2[i][c] & 0xffffffffULL));
            hi[c] = __uint_as_float((unsigned)(acc2[i][c] >> 32));
        }
        if (rowL < M)
            *(float4*)&g_Wh[(size_t)rowL * NHID + tx * 4] =
                make_float4(lo[0], lo[1], lo[2], lo[3]);
        if (rowH < M)
            *(float4*)&g_Wh[(size_t)rowH * NHID + tx * 4] =
                make_float4(hi[0], hi[1], hi[2], hi[3]);
        float siL = 0.f, sjL = 0.f, siH = 0.f, sjH = 0.f;
#pragma unroll
        for (int c = 0; c < 4; c++) {
            siL += lo[c] * awi[c];  sjL += lo[c] * awj[c];
            siH += hi[c] * awi[c];  sjH += hi[c] * awj[c];
        }
#pragma unroll
        for (int o = 8; o >= 1; o >>= 1) {
            siL += __shfl_xor_sync(0xffffffffu, siL, o);
            sjL += __shfl_xor_sync(0xffffffffu, sjL, o);
            siH += __shfl_xor_sync(0xffffffffu, siH, o);
            sjH += __shfl_xor_sync(0xffffffffu, sjH, o);
        }
        if (tx == 0) {
            if (rowL < M) { g_si[rowL] = siL; g_sj[rowL] = sjL; }
            if (rowH < M) { g_si[rowH] = siH; g_sj[rowH] = sjH; }
        }
    }
}

// ---------------- histogram of src ----------------
__global__ void hist_kernel(const void* __restrict__ ei, int E, int M) {
    int e = blockIdx.x * blockDim.x + threadIdx.x;
    if (e >= E) return;
    int s = load_idx(ei, e, g_idx64, M);
    atomicAdd(&g_count[s], 1);
}

// ---------------- exclusive scan over g_count (3 kernels) ----------------
__global__ void scan1_kernel(int M) {
    __shared__ int sm[256];
    int tid = threadIdx.x;
    int i = blockIdx.x * 256 + tid;
    int c = (i < M) ? g_count[i] : 0;
    sm[tid] = c;
    __syncthreads();
#pragma unroll
    for (int off = 1; off < 256; off <<= 1) {
        int v = (tid >= off) ? sm[tid - off] : 0;
        __syncthreads();
        sm[tid] += v;
        __syncthreads();
    }
    if (i < M) g_start[i] = sm[tid] - c;    // block-local exclusive
    if (tid == 255) g_bsum[blockIdx.x] = sm[255];
}

__global__ void scan2_kernel(int nb) {
    __shared__ int sm[512];
    int tid = threadIdx.x;
    int c = (tid < nb) ? g_bsum[tid] : 0;
    sm[tid] = c;
    __syncthreads();
#pragma unroll
    for (int off = 1; off < 512; off <<= 1) {
        int v = (tid >= off) ? sm[tid - off] : 0;
        __syncthreads();
        sm[tid] += v;
        __syncthreads();
    }
    g_boff[tid] = sm[tid] - c;              // exclusive block offsets
}

__global__ void scan3_kernel(int M, int E) {
    int i = blockIdx.x * 256 + threadIdx.x;
    if (i >= M) return;
    int v = g_start[i] + g_boff[blockIdx.x];
    g_start[i] = v;
    g_cursor[i] = v;
    if (i == M - 1) g_start[M] = E;
}

// ---------------- edge pass A (fused with reorder) ----------------
// computes h, accumulates h_sum, and writes h/dst/perm in src-sorted order.
__global__ void edgeA_fused_kernel(const void* __restrict__ ei,
                                   const float* __restrict__ ab, int E, int M) {
    int e = blockIdx.x * blockDim.x + threadIdx.x;
    if (e >= E) return;
    const int is64 = g_idx64;
    int s = load_idx(ei, e, is64, M);
    int d = load_idx(ei, (size_t)E + e, is64, M);
    float sc = g_si[s] + g_sj[d] + __ldg(&ab[0]);
    float l  = sc > 0.f ? sc : NEG_SLOPE * sc;
    float h  = expf(l);
    atomicAdd(&g_hsum[s], h);
    int pos = atomicAdd(&g_cursor[s], 1);
    g_hs[pos]   = h;
    g_dsts[pos] = d;
    g_perm[pos] = e;
}

// ---------------- reciprocal of h_sum ----------------
__global__ void recip_kernel(int M) {
    int n = blockIdx.x * blockDim.x + threadIdx.x;
    if (n >= M) return;
    g_hsum[n] = __frcp_rn(g_hsum[n]);
}

// ---------------- edge pass B: CSR gather, warp per node ----------------
// 16 lanes per edge (float4 each); 2 edges per warp-iteration.
// Output row written ONCE with plain stores -> zero atomics.
__global__ void __launch_bounds__(256) edgeB_csr_kernel(
        float* __restrict__ out,
        float* __restrict__ alpha_out, int M) {
    int warp = (blockIdx.x * blockDim.x + threadIdx.x) >> 5;
    if (warp >= M) return;
    int lane = threadIdx.x & 31;
    int sub  = lane >> 4;                  // 0/1: which edge of the pair
    int part = lane & 15;                  // float4 index within row

    int start = g_start[warp];
    int end   = g_start[warp + 1];
    float rinv = g_hsum[warp];             // reciprocal of h_sum

    float4 acc = make_float4(0.f, 0.f, 0.f, 0.f);
    for (int pos = start + sub; pos < end; pos += 2) {
        int   d     = g_dsts[pos];
        float alpha = g_hs[pos] * rinv;
        if (part == 0 && alpha_out) alpha_out[g_perm[pos]] = alpha;
        float4 w = *(const float4*)&g_Wh[(size_t)d * NHID + part * 4];
        acc.x += alpha * w.x;
        acc.y += alpha * w.y;
        acc.z += alpha * w.z;
        acc.w += alpha * w.w;
    }
    // fold sub=1 into sub=0
    acc.x += __shfl_down_sync(0xffffffffu, acc.x, 16);
    acc.y += __shfl_down_sync(0xffffffffu, acc.y, 16);
    acc.z += __shfl_down_sync(0xffffffffu, acc.z, 16);
    acc.w += __shfl_down_sync(0xffffffffu, acc.w, 16);
    if (sub == 0)
        *(float4*)&out[(size_t)warp * NHID + part * 4] = acc;
}

// ---------------- launch ----------------
extern "C" void kernel_launch(void* const* d_in, const int* in_sizes, int n_in,
                              void* d_out, int out_size) {
    const float* x  = (const float*)d_in[0];
    const float* W  = (const float*)d_in[1];
    const float* aw = (const float*)d_in[2];
    const float* ab = (const float*)d_in[3];
    const void*  ei = d_in[4];

    const int M = in_sizes[0] / NFEAT;       // 100000
    const int E = in_sizes[4] / 2;           // 1600000

    float* out       = (float*)d_out;                    // [M, 64]
    float* alpha_out = (out_size >= M * NHID + E) ? out + (size_t)M * NHID : nullptr;

    const int nb = (M + 255) / 256;          // scan blocks (<=512 required)

    detect_kernel<<<1, 256>>>(ei, E, M);
    zero_small_kernel<<<nb, 256>>>(M);
    gemm_kernel<<<(M + BM - 1) / BM, 256>>>(x, W, aw, M);
    hist_kernel<<<(E + 255) / 256, 256>>>(ei, E, M);
    scan1_kernel<<<nb, 256>>>(M);
    scan2_kernel<<<1, 512>>>(nb);
    scan3_kernel<<<nb, 256>>>(M, E);
    edgeA_fused_kernel<<<(E + 255) / 256, 256>>>(ei, ab, E, M);
    recip_kernel<<<nb, 256>>>(M);
    edgeB_csr_kernel<<<(M * 32 + 255) / 256, 256>>>(out, alpha_out, M);
}

// round 7
// speedup vs baseline: 1.1129x; 1.1036x over previous
#include <cuda_runtime.h>
#include <cstdint>

#define NFEAT 256
#define NHID 64
#define NEG_SLOPE 0.05f
#define MAX_N 100000
#define MAX_E 1600000
#define BM 128
#define BK 32

// ---------------- device scratch (no allocation allowed) ----------------
__device__ float  g_Wh[(size_t)MAX_N * NHID];   // 25.6 MB
__device__ float  g_si[MAX_N];
__device__ float  g_sj[MAX_N];
__device__ float  g_hsum[MAX_N];                // later holds reciprocal
__device__ float  g_h[MAX_E];                   // h in ORIGINAL edge order
__device__ int    g_idx64;                      // 1 if edge_index is int64
// CSR build
__device__ int    g_count[MAX_N];
__device__ int    g_start[MAX_N + 1];
__device__ int    g_cursor[MAX_N];
__device__ int    g_bsum[512];
__device__ int    g_boff[512];
__device__ float2 g_pack[MAX_E];                // {h, dst-as-bits} in src-sorted order

// ---------------- index helper: dtype-adaptive, clamped ----------------
__device__ __forceinline__ int load_idx(const void* ei, size_t pos, int is64, int M) {
    int v;
    if (is64) v = (int)((const long long*)ei)[pos];
    else      v = ((const int*)ei)[pos];
    v = v < 0 ? 0 : (v >= M ? M - 1 : v);
    return v;
}

// ---------------- detect edge_index dtype ----------------
__global__ void detect_kernel(const void* ei, int E, int M) {
    __shared__ int bad;
    if (threadIdx.x == 0) bad = 0;
    __syncthreads();
    const long long* p = (const long long*)ei;
    int stride = E / 4096 > 0 ? E / 4096 : 1;
    for (int i = threadIdx.x; i < 4096; i += blockDim.x) {
        size_t pos = (size_t)i * stride;
        if (pos < (size_t)E) {
            long long v = p[pos];
            if (v < 0 || v >= M) atomicOr(&bad, 1);
        }
    }
    __syncthreads();
    if (threadIdx.x == 0) g_idx64 = bad ? 0 : 1;
}

// ---------------- zero small per-node arrays ----------------
__global__ void zero_small_kernel(int M) {
    int i = blockIdx.x * blockDim.x + threadIdx.x;
    if (i < M) { g_hsum[i] = 0.f; g_count[i] = 0; }
}

// ---------------- histogram of src ----------------
__global__ void hist_kernel(const void* __restrict__ ei, int E, int M) {
    int e = blockIdx.x * blockDim.x + threadIdx.x;
    if (e >= E) return;
    int s = load_idx(ei, e, g_idx64, M);
    atomicAdd(&g_count[s], 1);
}

// ---------------- GEMM: Wh = x @ W_fc (FFMA2) + fused score ----------------
// (launch index 3 -> this is the kernel ncu captures this round)
__global__ void __launch_bounds__(256) gemm_kernel(
        const float* __restrict__ x,
        const float* __restrict__ W,
        const float* __restrict__ aw,
        int M) {
    __shared__ float As[BK][BM];
    __shared__ float Bs2[BK][128];

    const int tid = threadIdx.x;
    const int tx  = tid & 15;
    const int ty  = tid >> 4;
    const int g   = (tx >> 2) & 3;
    const int m0  = blockIdx.x * BM;

    unsigned long long acc2[4][4];
#pragma unroll
    for (int i = 0; i < 4; i++)
#pragma unroll
        for (int c = 0; c < 4; c++) acc2[i][c] = 0ULL;

    for (int k0 = 0; k0 < NFEAT; k0 += BK) {
#pragma unroll
        for (int p = 0; p < 4; p++) {
            int idx = p * 256 + tid;
            int row = idx >> 3;
            int kc  = (idx & 7) * 4;
            float4 v = make_float4(0.f, 0.f, 0.f, 0.f);
            int gm = m0 + row;
            if (gm < M) v = *(const float4*)&x[(size_t)gm * NFEAT + k0 + kc];
            As[kc + 0][row] = v.x;
            As[kc + 1][row] = v.y;
            As[kc + 2][row] = v.z;
            As[kc + 3][row] = v.w;
        }
#pragma unroll
        for (int p = 0; p < 8; p++) {
            int idx = p * 256 + tid;
            int k = idx >> 6;
            int j = idx & 63;
            float v = W[(size_t)(k0 + k) * NHID + j];
            int col = ((j >> 2) << 3) + ((((j & 3) ^ ((j >> 4) & 3))) << 1);
            Bs2[k][col]     = v;
            Bs2[k][col + 1] = v;
        }
        __syncthreads();

#pragma unroll
        for (int k = 0; k < BK; k++) {
            ulonglong2 aL = *(const ulonglong2*)&As[k][ty * 8];
            ulonglong2 aH = *(const ulonglong2*)&As[k][ty * 8 + 4];
            unsigned long long ap[4] = {aL.x, aL.y, aH.x, aH.y};
            unsigned long long bp[4];
#pragma unroll
            for (int c = 0; c < 4; c++)
                bp[c] = *(const unsigned long long*)&Bs2[k][tx * 8 + ((c ^ g) << 1)];
#pragma unroll
            for (int i = 0; i < 4; i++)
#pragma unroll
                for (int c = 0; c < 4; c++)
                    asm("fma.rn.f32x2 %0, %1, %2, %0;"
                        : "+l"(acc2[i][c]) : "l"(ap[i]), "l"(bp[c]));
        }
        __syncthreads();
    }

    float awi[4], awj[4];
#pragma unroll
    for (int c = 0; c < 4; c++) {
        awi[c] = __ldg(&aw[tx * 4 + c]);
        awj[c] = __ldg(&aw[64 + tx * 4 + c]);
    }
#pragma unroll
    for (int i = 0; i < 4; i++) {
        int rowL = m0 + ty * 8 + i * 2;
        int rowH = rowL + 1;
        float lo[4], hi[4];
#pragma unroll
        for (int c = 0; c < 4; c++) {
            lo[c] = __uint_as_float((unsigned)(acc2[i][c] & 0xffffffffULL));
            hi[c] = __uint_as_float((unsigned)(acc2[i][c] >> 32));
        }
        if (rowL < M)
            *(float4*)&g_Wh[(size_t)rowL * NHID + tx * 4] =
                make_float4(lo[0], lo[1], lo[2], lo[3]);
        if (rowH < M)
            *(float4*)&g_Wh[(size_t)rowH * NHID + tx * 4] =
                make_float4(hi[0], hi[1], hi[2], hi[3]);
        float siL = 0.f, sjL = 0.f, siH = 0.f, sjH = 0.f;
#pragma unroll
        for (int c = 0; c < 4; c++) {
            siL += lo[c] * awi[c];  sjL += lo[c] * awj[c];
            siH += hi[c] * awi[c];  sjH += hi[c] * awj[c];
        }
#pragma unroll
        for (int o = 8; o >= 1; o >>= 1) {
            siL += __shfl_xor_sync(0xffffffffu, siL, o);
            sjL += __shfl_xor_sync(0xffffffffu, sjL, o);
            siH += __shfl_xor_sync(0xffffffffu, siH, o);
            sjH += __shfl_xor_sync(0xffffffffu, sjH, o);
        }
        if (tx == 0) {
            if (rowL < M) { g_si[rowL] = siL; g_sj[rowL] = sjL; }
            if (rowH < M) { g_si[rowH] = siH; g_sj[rowH] = sjH; }
        }
    }
}

// ---------------- exclusive scan over g_count (3 kernels) ----------------
__global__ void scan1_kernel(int M) {
    __shared__ int sm[256];
    int tid = threadIdx.x;
    int i = blockIdx.x * 256 + tid;
    int c = (i < M) ? g_count[i] : 0;
    sm[tid] = c;
    __syncthreads();
#pragma unroll
    for (int off = 1; off < 256; off <<= 1) {
        int v = (tid >= off) ? sm[tid - off] : 0;
        __syncthreads();
        sm[tid] += v;
        __syncthreads();
    }
    if (i < M) g_start[i] = sm[tid] - c;
    if (tid == 255) g_bsum[blockIdx.x] = sm[255];
}

__global__ void scan2_kernel(int nb) {
    __shared__ int sm[512];
    int tid = threadIdx.x;
    int c = (tid < nb) ? g_bsum[tid] : 0;
    sm[tid] = c;
    __syncthreads();
#pragma unroll
    for (int off = 1; off < 512; off <<= 1) {
        int v = (tid >= off) ? sm[tid - off] : 0;
        __syncthreads();
        sm[tid] += v;
        __syncthreads();
    }
    g_boff[tid] = sm[tid] - c;
}

__global__ void scan3_kernel(int M, int E) {
    int i = blockIdx.x * 256 + threadIdx.x;
    if (i >= M) return;
    int v = g_start[i] + g_boff[blockIdx.x];
    g_start[i] = v;
    g_cursor[i] = v;
    if (i == M - 1) g_start[M] = E;
}

// ---------------- edge pass A: h + hsum + sorted pack write ----------------
__global__ void edgeA_fused_kernel(const void* __restrict__ ei,
                                   const float* __restrict__ ab, int E, int M) {
    int e = blockIdx.x * blockDim.x + threadIdx.x;
    if (e >= E) return;
    const int is64 = g_idx64;
    int s = load_idx(ei, e, is64, M);
    int d = load_idx(ei, (size_t)E + e, is64, M);
    float sc = g_si[s] + g_sj[d] + __ldg(&ab[0]);
    float l  = sc > 0.f ? sc : NEG_SLOPE * sc;
    float h  = expf(l);
    g_h[e] = h;                               // coalesced, for alpha pass
    atomicAdd(&g_hsum[s], h);
    int pos = atomicAdd(&g_cursor[s], 1);
    g_pack[pos] = make_float2(h, __int_as_float(d));   // one 8B scattered store
}

// ---------------- reciprocal of h_sum ----------------
__global__ void recip_kernel(int M) {
    int n = blockIdx.x * blockDim.x + threadIdx.x;
    if (n >= M) return;
    g_hsum[n] = __frcp_rn(g_hsum[n]);
}

// ---------------- alpha in original edge order (fully coalesced) --------
__global__ void alpha_kernel(const void* __restrict__ ei,
                             float* __restrict__ alpha_out, int E, int M) {
    int e = blockIdx.x * blockDim.x + threadIdx.x;
    if (e >= E) return;
    int s = load_idx(ei, e, g_idx64, M);
    alpha_out[e] = g_h[e] * g_hsum[s];
}

// ---------------- edge pass B: CSR gather, warp per node ----------------
__global__ void __launch_bounds__(256) edgeB_csr_kernel(
        float* __restrict__ out, int M) {
    int warp = (blockIdx.x * blockDim.x + threadIdx.x) >> 5;
    if (warp >= M) return;
    int lane = threadIdx.x & 31;
    int sub  = lane >> 4;                  // which edge of the pair
    int part = lane & 15;                  // float4 index within row

    int start = g_start[warp];
    int end   = g_start[warp + 1];
    float rinv = g_hsum[warp];             // reciprocal of h_sum

    float4 acc = make_float4(0.f, 0.f, 0.f, 0.f);
    for (int pos = start + sub; pos < end; pos += 2) {
        float2 p    = g_pack[pos];         // one LDG.64, broadcast across 16 lanes
        int    d    = __float_as_int(p.y);
        float alpha = p.x * rinv;
        float4 w = *(const float4*)&g_Wh[(size_t)d * NHID + part * 4];
        acc.x += alpha * w.x;
        acc.y += alpha * w.y;
        acc.z += alpha * w.z;
        acc.w += alpha * w.w;
    }
    acc.x += __shfl_down_sync(0xffffffffu, acc.x, 16);
    acc.y += __shfl_down_sync(0xffffffffu, acc.y, 16);
    acc.z += __shfl_down_sync(0xffffffffu, acc.z, 16);
    acc.w += __shfl_down_sync(0xffffffffu, acc.w, 16);
    if (sub == 0)
        *(float4*)&out[(size_t)warp * NHID + part * 4] = acc;
}

// ---------------- launch ----------------
extern "C" void kernel_launch(void* const* d_in, const int* in_sizes, int n_in,
                              void* d_out, int out_size) {
    const float* x  = (const float*)d_in[0];
    const float* W  = (const float*)d_in[1];
    const float* aw = (const float*)d_in[2];
    const float* ab = (const float*)d_in[3];
    const void*  ei = d_in[4];

    const int M = in_sizes[0] / NFEAT;       // 100000
    const int E = in_sizes[4] / 2;           // 1600000

    float* out       = (float*)d_out;                    // [M, 64]
    float* alpha_out = (out_size >= M * NHID + E) ? out + (size_t)M * NHID : nullptr;

    const int nb = (M + 255) / 256;          // scan blocks (<=512)

    // order chosen so gemm_kernel is launch index 3 (ncu captures index 3)
    detect_kernel<<<1, 256>>>(ei, E, M);                       // 0
    zero_small_kernel<<<nb, 256>>>(M);                         // 1
    hist_kernel<<<(E + 255) / 256, 256>>>(ei, E, M);           // 2
    gemm_kernel<<<(M + BM - 1) / BM, 256>>>(x, W, aw, M);      // 3  <- profiled
    scan1_kernel<<<nb, 256>>>(M);                              // 4
    scan2_kernel<<<1, 512>>>(nb);                              // 5
    scan3_kernel<<<nb, 256>>>(M, E);                           // 6
    edgeA_fused_kernel<<<(E + 255) / 256, 256>>>(ei, ab, E, M);// 7
    recip_kernel<<<nb, 256>>>(M);                              // 8
    if (alpha_out)
        alpha_kernel<<<(E + 255) / 256, 256>>>(ei, alpha_out, E, M); // 9
    edgeB_csr_kernel<<<(M * 32 + 255) / 256, 256>>>(out, M);   // 10
}

// round 8
// speedup vs baseline: 1.1757x; 1.0564x over previous
#include <cuda_runtime.h>
#include <cstdint>

#define NFEAT 256
#define NHID 64
#define NEG_SLOPE 0.05f
#define MAX_N 100000
#define MAX_E 1600000
#define BM 256
#define BK 16

// ---------------- device scratch (no allocation allowed) ----------------
__device__ float  g_Wh[(size_t)MAX_N * NHID];   // 25.6 MB
__device__ float  g_si[MAX_N];
__device__ float  g_sj[MAX_N];
__device__ float  g_hsum[MAX_N];                // later holds reciprocal
__device__ float  g_h[MAX_E];                   // h in ORIGINAL edge order
__device__ int    g_idx64;                      // 1 if edge_index is int64
// CSR build
__device__ int    g_count[MAX_N];
__device__ int    g_start[MAX_N + 1];
__device__ int    g_cursor[MAX_N];
__device__ int    g_bsum[512];
__device__ int    g_boff[512];
__device__ float2 g_pack[MAX_E];                // {h, dst-as-bits} src-sorted

// ---------------- index helper: dtype-adaptive, clamped ----------------
__device__ __forceinline__ int load_idx(const void* ei, size_t pos, int is64, int M) {
    int v;
    if (is64) v = (int)((const long long*)ei)[pos];
    else      v = ((const int*)ei)[pos];
    v = v < 0 ? 0 : (v >= M ? M - 1 : v);
    return v;
}

// ---------------- detect edge_index dtype ----------------
__global__ void detect_kernel(const void* ei, int E, int M) {
    __shared__ int bad;
    if (threadIdx.x == 0) bad = 0;
    __syncthreads();
    const long long* p = (const long long*)ei;
    int stride = E / 4096 > 0 ? E / 4096 : 1;
    for (int i = threadIdx.x; i < 4096; i += blockDim.x) {
        size_t pos = (size_t)i * stride;
        if (pos < (size_t)E) {
            long long v = p[pos];
            if (v < 0 || v >= M) atomicOr(&bad, 1);
        }
    }
    __syncthreads();
    if (threadIdx.x == 0) g_idx64 = bad ? 0 : 1;
}

// ---------------- zero small per-node arrays ----------------
__global__ void zero_small_kernel(int M) {
    int i = blockIdx.x * blockDim.x + threadIdx.x;
    if (i < M) { g_hsum[i] = 0.f; g_count[i] = 0; }
}

// ---------------- histogram of src ----------------
__global__ void hist_kernel(const void* __restrict__ ei, int E, int M) {
    int e = blockIdx.x * blockDim.x + threadIdx.x;
    if (e >= E) return;
    int s = load_idx(ei, e, g_idx64, M);
    atomicAdd(&g_count[s], 1);
}

// ---------------- GEMM: Wh = x @ W_fc, FFMA2 w/ col-paired acc ----------
// BM=256, BN=64, BK=16, 256 threads, 8x8 microtile per thread.
// acc2[r][cp] = (out[r][2cp], out[r][2cp+1]); B pairs come natural from
// plain Bs via LDS.128; A splat pairs built with mov.b64 {a,a}.
// LDS traffic: 64B per 64 MACs = 1.0 B/MAC (was 1.5).
__global__ void __launch_bounds__(256) gemm_kernel(
        const float* __restrict__ x,
        const float* __restrict__ W,
        const float* __restrict__ aw,
        int M) {
    __shared__ float As[BK][BM];     // [k][m] transposed, 16KB
    __shared__ float Bs[BK][NHID];   // [k][n], 4KB

    const int tid = threadIdx.x;
    const int tx  = tid & 7;         // col group 0..7  -> cols tx*8..+7
    const int ty  = tid >> 3;        // row group 0..31 -> rows ty*8..+7
    const int m0  = blockIdx.x * BM;

    unsigned long long acc2[8][4];
#pragma unroll
    for (int r = 0; r < 8; r++)
#pragma unroll
        for (int c = 0; c < 4; c++) acc2[r][c] = 0ULL;

    for (int k0 = 0; k0 < NFEAT; k0 += BK) {
        // A tile: 256 rows x 16 k, transposed; 4 float4 per thread
#pragma unroll
        for (int p = 0; p < 4; p++) {
            int idx = p * 256 + tid;       // 0..1023
            int row = idx >> 2;            // 0..255
            int kc  = (idx & 3) * 4;       // 0,4,8,12
            float4 v = make_float4(0.f, 0.f, 0.f, 0.f);
            int gm = m0 + row;
            if (gm < M) v = *(const float4*)&x[(size_t)gm * NFEAT + k0 + kc];
            As[kc + 0][row] = v.x;
            As[kc + 1][row] = v.y;
            As[kc + 2][row] = v.z;
            As[kc + 3][row] = v.w;
        }
        // B tile: 16 x 64, 1 float4 per thread
        {
            int k = tid >> 4;              // 0..15
            int j = (tid & 15) * 4;        // 0..60
            *(float4*)&Bs[k][j] = *(const float4*)&W[(size_t)(k0 + k) * NHID + j];
        }
        __syncthreads();

#pragma unroll
        for (int k = 0; k < BK; k++) {
            float4 aL = *(const float4*)&As[k][ty * 8];
            float4 aH = *(const float4*)&As[k][ty * 8 + 4];
            ulonglong2 bL = *(const ulonglong2*)&Bs[k][tx * 8];
            ulonglong2 bH = *(const ulonglong2*)&Bs[k][tx * 8 + 4];
            unsigned long long bp[4] = {bL.x, bL.y, bH.x, bH.y};
            unsigned avu[8] = {
                __float_as_uint(aL.x), __float_as_uint(aL.y),
                __float_as_uint(aL.z), __float_as_uint(aL.w),
                __float_as_uint(aH.x), __float_as_uint(aH.y),
                __float_as_uint(aH.z), __float_as_uint(aH.w)};
            unsigned long long ap[8];
#pragma unroll
            for (int r = 0; r < 8; r++)
                asm("mov.b64 %0, {%1, %1};" : "=l"(ap[r]) : "r"(avu[r]));
#pragma unroll
            for (int r = 0; r < 8; r++)
#pragma unroll
                for (int c = 0; c < 4; c++)
                    asm("fma.rn.f32x2 %0, %1, %2, %0;"
                        : "+l"(acc2[r][c]) : "l"(ap[r]), "l"(bp[c]));
        }
        __syncthreads();
    }

    // epilogue: store Wh + fused score reduction over tx (8 lanes)
    float awi[8], awj[8];
#pragma unroll
    for (int c = 0; c < 8; c++) {
        awi[c] = __ldg(&aw[tx * 8 + c]);
        awj[c] = __ldg(&aw[64 + tx * 8 + c]);
    }
#pragma unroll
    for (int r = 0; r < 8; r++) {
        int row = m0 + ty * 8 + r;
        float v[8];
#pragma unroll
        for (int c = 0; c < 4; c++) {
            v[2 * c]     = __uint_as_float((unsigned)(acc2[r][c] & 0xffffffffULL));
            v[2 * c + 1] = __uint_as_float((unsigned)(acc2[r][c] >> 32));
        }
        if (row < M) {
            *(float4*)&g_Wh[(size_t)row * NHID + tx * 8] =
                make_float4(v[0], v[1], v[2], v[3]);
            *(float4*)&g_Wh[(size_t)row * NHID + tx * 8 + 4] =
                make_float4(v[4], v[5], v[6], v[7]);
        }
        float si = 0.f, sj = 0.f;
#pragma unroll
        for (int c = 0; c < 8; c++) { si += v[c] * awi[c]; sj += v[c] * awj[c]; }
#pragma unroll
        for (int o = 4; o >= 1; o >>= 1) {
            si += __shfl_xor_sync(0xffffffffu, si, o);
            sj += __shfl_xor_sync(0xffffffffu, sj, o);
        }
        if (tx == 0 && row < M) { g_si[row] = si; g_sj[row] = sj; }
    }
}

// ---------------- exclusive scan over g_count (3 kernels) ----------------
__global__ void scan1_kernel(int M) {
    __shared__ int sm[256];
    int tid = threadIdx.x;
    int i = blockIdx.x * 256 + tid;
    int c = (i < M) ? g_count[i] : 0;
    sm[tid] = c;
    __syncthreads();
#pragma unroll
    for (int off = 1; off < 256; off <<= 1) {
        int v = (tid >= off) ? sm[tid - off] : 0;
        __syncthreads();
        sm[tid] += v;
        __syncthreads();
    }
    if (i < M) g_start[i] = sm[tid] - c;
    if (tid == 255) g_bsum[blockIdx.x] = sm[255];
}

__global__ void scan2_kernel(int nb) {
    __shared__ int sm[512];
    int tid = threadIdx.x;
    int c = (tid < nb) ? g_bsum[tid] : 0;
    sm[tid] = c;
    __syncthreads();
#pragma unroll
    for (int off = 1; off < 512; off <<= 1) {
        int v = (tid >= off) ? sm[tid - off] : 0;
        __syncthreads();
        sm[tid] += v;
        __syncthreads();
    }
    g_boff[tid] = sm[tid] - c;
}

__global__ void scan3_kernel(int M, int E) {
    int i = blockIdx.x * 256 + threadIdx.x;
    if (i >= M) return;
    int v = g_start[i] + g_boff[blockIdx.x];
    g_start[i] = v;
    g_cursor[i] = v;
    if (i == M - 1) g_start[M] = E;
}

// ---------------- edge pass A: h + hsum + sorted pack write ----------------
__global__ void edgeA_fused_kernel(const void* __restrict__ ei,
                                   const float* __restrict__ ab, int E, int M) {
    int e = blockIdx.x * blockDim.x + threadIdx.x;
    if (e >= E) return;
    const int is64 = g_idx64;
    int s = load_idx(ei, e, is64, M);
    int d = load_idx(ei, (size_t)E + e, is64, M);
    float sc = g_si[s] + g_sj[d] + __ldg(&ab[0]);
    float l  = sc > 0.f ? sc : NEG_SLOPE * sc;
    float h  = expf(l);
    g_h[e] = h;
    atomicAdd(&g_hsum[s], h);
    int pos = atomicAdd(&g_cursor[s], 1);
    g_pack[pos] = make_float2(h, __int_as_float(d));
}

// ---------------- reciprocal of h_sum ----------------
__global__ void recip_kernel(int M) {
    int n = blockIdx.x * blockDim.x + threadIdx.x;
    if (n >= M) return;
    g_hsum[n] = __frcp_rn(g_hsum[n]);
}

// ---------------- alpha in original edge order (fully coalesced) --------
__global__ void alpha_kernel(const void* __restrict__ ei,
                             float* __restrict__ alpha_out, int E, int M) {
    int e = blockIdx.x * blockDim.x + threadIdx.x;
    if (e >= E) return;
    int s = load_idx(ei, e, g_idx64, M);
    alpha_out[e] = g_h[e] * g_hsum[s];
}

// ---------------- edge pass B: CSR gather, warp per node ----------------
__global__ void __launch_bounds__(256) edgeB_csr_kernel(
        float* __restrict__ out, int M) {
    int warp = (blockIdx.x * blockDim.x + threadIdx.x) >> 5;
    if (warp >= M) return;
    int lane = threadIdx.x & 31;
    int sub  = lane >> 4;
    int part = lane & 15;

    int start = g_start[warp];
    int end   = g_start[warp + 1];
    float rinv = g_hsum[warp];

    float4 acc = make_float4(0.f, 0.f, 0.f, 0.f);
    for (int pos = start + sub; pos < end; pos += 2) {
        float2 p    = g_pack[pos];
        int    d    = __float_as_int(p.y);
        float alpha = p.x * rinv;
        float4 w = *(const float4*)&g_Wh[(size_t)d * NHID + part * 4];
        acc.x += alpha * w.x;
        acc.y += alpha * w.y;
        acc.z += alpha * w.z;
        acc.w += alpha * w.w;
    }
    acc.x += __shfl_down_sync(0xffffffffu, acc.x, 16);
    acc.y += __shfl_down_sync(0xffffffffu, acc.y, 16);
    acc.z += __shfl_down_sync(0xffffffffu, acc.z, 16);
    acc.w += __shfl_down_sync(0xffffffffu, acc.w, 16);
    if (sub == 0)
        *(float4*)&out[(size_t)warp * NHID + part * 4] = acc;
}

// ---------------- launch ----------------
extern "C" void kernel_launch(void* const* d_in, const int* in_sizes, int n_in,
                              void* d_out, int out_size) {
    const float* x  = (const float*)d_in[0];
    const float* W  = (const float*)d_in[1];
    const float* aw = (const float*)d_in[2];
    const float* ab = (const float*)d_in[3];
    const void*  ei = d_in[4];

    const int M = in_sizes[0] / NFEAT;       // 100000
    const int E = in_sizes[4] / 2;           // 1600000

    float* out       = (float*)d_out;                    // [M, 64]
    float* alpha_out = (out_size >= M * NHID + E) ? out + (size_t)M * NHID : nullptr;

    const int nb = (M + 255) / 256;          // scan blocks (<=512)

    // order keeps gemm_kernel at launch index 3 (ncu captures index 3)
    detect_kernel<<<1, 256>>>(ei, E, M);                       // 0
    zero_small_kernel<<<nb, 256>>>(M);                         // 1
    hist_kernel<<<(E + 255) / 256, 256>>>(ei, E, M);           // 2
    gemm_kernel<<<(M + BM - 1) / BM, 256>>>(x, W, aw, M);      // 3  <- profiled
    scan1_kernel<<<nb, 256>>>(M);                              // 4
    scan2_kernel<<<1, 512>>>(nb);                              // 5
    scan3_kernel<<<nb, 256>>>(M, E);                           // 6
    edgeA_fused_kernel<<<(E + 255) / 256, 256>>>(ei, ab, E, M);// 7
    recip_kernel<<<nb, 256>>>(M);                              // 8
    if (alpha_out)
        alpha_kernel<<<(E + 255) / 256, 256>>>(ei, alpha_out, E, M); // 9
    edgeB_csr_kernel<<<(M * 32 + 255) / 256, 256>>>(out, M);   // 10
}

// round 9
// speedup vs baseline: 1.2025x; 1.0228x over previous
#include <cuda_runtime.h>
#include <cstdint>

#define NFEAT 256
#define NHID 64
#define NEG_SLOPE 0.05f
#define MAX_N 100000
#define MAX_E 1600000
#define BM 256
#define BK 16
#define NTILE (NFEAT / BK)

// ---------------- device scratch (no allocation allowed) ----------------
__device__ float  g_Wh[(size_t)MAX_N * NHID];   // 25.6 MB
__device__ float  g_si[MAX_N];
__device__ float  g_sj[MAX_N];
__device__ float  g_hsum[MAX_N];                // later holds reciprocal
__device__ float  g_h[MAX_E];                   // h in ORIGINAL edge order
__device__ int    g_idx64;                      // 1 if edge_index is int64
// CSR build
__device__ int    g_count[MAX_N];
__device__ int    g_start[MAX_N + 1];
__device__ int    g_cursor[MAX_N];
__device__ int    g_bsum[512];
__device__ int    g_boff[512];
__device__ float2 g_pack[MAX_E];                // {h, dst-as-bits} src-sorted

// ---------------- index helper: dtype-adaptive, clamped ----------------
__device__ __forceinline__ int load_idx(const void* ei, size_t pos, int is64, int M) {
    int v;
    if (is64) v = (int)((const long long*)ei)[pos];
    else      v = ((const int*)ei)[pos];
    v = v < 0 ? 0 : (v >= M ? M - 1 : v);
    return v;
}

// ---------------- detect edge_index dtype ----------------
__global__ void detect_kernel(const void* ei, int E, int M) {
    __shared__ int bad;
    if (threadIdx.x == 0) bad = 0;
    __syncthreads();
    const long long* p = (const long long*)ei;
    int stride = E / 4096 > 0 ? E / 4096 : 1;
    for (int i = threadIdx.x; i < 4096; i += blockDim.x) {
        size_t pos = (size_t)i * stride;
        if (pos < (size_t)E) {
            long long v = p[pos];
            if (v < 0 || v >= M) atomicOr(&bad, 1);
        }
    }
    __syncthreads();
    if (threadIdx.x == 0) g_idx64 = bad ? 0 : 1;
}

// ---------------- zero small per-node arrays ----------------
__global__ void zero_small_kernel(int M) {
    int i = blockIdx.x * blockDim.x + threadIdx.x;
    if (i < M) { g_hsum[i] = 0.f; g_count[i] = 0; }
}

// ---------------- histogram of src ----------------
__global__ void hist_kernel(const void* __restrict__ ei, int E, int M) {
    int e = blockIdx.x * blockDim.x + threadIdx.x;
    if (e >= E) return;
    int s = load_idx(ei, e, g_idx64, M);
    atomicAdd(&g_count[s], 1);
}

// ---------------- GEMM: Wh = x @ W_fc, FFMA2, double-buffered ----------
// BM=256, BN=64, BK=16, 256 threads, 8x8 microtile per thread.
// Software pipeline: LDG next tile -> compute current -> STS -> 1 barrier.
__global__ void __launch_bounds__(256, 2) gemm_kernel(
        const float* __restrict__ x,
        const float* __restrict__ W,
        const float* __restrict__ aw,
        int M) {
    __shared__ float As[2][BK][BM];   // 2 x 16KB
    __shared__ float Bs[2][BK][NHID]; // 2 x 4KB

    const int tid = threadIdx.x;
    const int tx  = tid & 7;          // col group 0..7
    const int ty  = tid >> 3;         // row group 0..31
    const int m0  = blockIdx.x * BM;

    // A-load mapping: this thread covers 4 (row, kc) slots per tile
    int arow[4], akc[4], aval[4];
    const float* aptr[4];
#pragma unroll
    for (int p = 0; p < 4; p++) {
        int idx = p * 256 + tid;        // 0..1023
        arow[p] = idx >> 2;             // 0..255
        akc[p]  = (idx & 3) * 4;        // 0,4,8,12
        int gm  = m0 + arow[p];
        aval[p] = gm < M;
        aptr[p] = x + (size_t)(aval[p] ? gm : 0) * NFEAT + akc[p];
    }
    const int bk = tid >> 4, bj = (tid & 15) * 4;
    const float* bptr = W + (size_t)bk * NHID + bj;

    float4 astg[4], bstg;
#pragma unroll
    for (int p = 0; p < 4; p++)
        astg[p] = aval[p] ? *(const float4*)aptr[p]
                          : make_float4(0.f, 0.f, 0.f, 0.f);
    bstg = *(const float4*)bptr;

    // store tile 0 into buffer 0
#pragma unroll
    for (int p = 0; p < 4; p++) {
        As[0][akc[p] + 0][arow[p]] = astg[p].x;
        As[0][akc[p] + 1][arow[p]] = astg[p].y;
        As[0][akc[p] + 2][arow[p]] = astg[p].z;
        As[0][akc[p] + 3][arow[p]] = astg[p].w;
    }
    *(float4*)&Bs[0][bk][bj] = bstg;
    __syncthreads();

    unsigned long long acc2[8][4];
#pragma unroll
    for (int r = 0; r < 8; r++)
#pragma unroll
        for (int c = 0; c < 4; c++) acc2[r][c] = 0ULL;

#pragma unroll 2
    for (int t = 0; t < NTILE; t++) {
        const int buf = t & 1;
        // prefetch next tile into registers (overlaps with compute below)
        if (t + 1 < NTILE) {
#pragma unroll
            for (int p = 0; p < 4; p++)
                astg[p] = aval[p] ? *(const float4*)(aptr[p] + (t + 1) * BK)
                                  : make_float4(0.f, 0.f, 0.f, 0.f);
            bstg = *(const float4*)(bptr + (size_t)(t + 1) * BK * NHID);
        }
        // compute on current buffer
#pragma unroll
        for (int k = 0; k < BK; k++) {
            float4 aL = *(const float4*)&As[buf][k][ty * 8];
            float4 aH = *(const float4*)&As[buf][k][ty * 8 + 4];
            ulonglong2 bL = *(const ulonglong2*)&Bs[buf][k][tx * 8];
            ulonglong2 bH = *(const ulonglong2*)&Bs[buf][k][tx * 8 + 4];
            unsigned long long bp[4] = {bL.x, bL.y, bH.x, bH.y};
            unsigned avu[8] = {
                __float_as_uint(aL.x), __float_as_uint(aL.y),
                __float_as_uint(aL.z), __float_as_uint(aL.w),
                __float_as_uint(aH.x), __float_as_uint(aH.y),
                __float_as_uint(aH.z), __float_as_uint(aH.w)};
            unsigned long long ap[8];
#pragma unroll
            for (int r = 0; r < 8; r++)
                asm("mov.b64 %0, {%1, %1};" : "=l"(ap[r]) : "r"(avu[r]));
#pragma unroll
            for (int r = 0; r < 8; r++)
#pragma unroll
                for (int c = 0; c < 4; c++)
                    asm("fma.rn.f32x2 %0, %1, %2, %0;"
                        : "+l"(acc2[r][c]) : "l"(ap[r]), "l"(bp[c]));
        }
        // publish next tile
        if (t + 1 < NTILE) {
            const int nb = buf ^ 1;
#pragma unroll
            for (int p = 0; p < 4; p++) {
                As[nb][akc[p] + 0][arow[p]] = astg[p].x;
                As[nb][akc[p] + 1][arow[p]] = astg[p].y;
                As[nb][akc[p] + 2][arow[p]] = astg[p].z;
                As[nb][akc[p] + 3][arow[p]] = astg[p].w;
            }
            *(float4*)&Bs[nb][bk][bj] = bstg;
            __syncthreads();
        }
    }

    // epilogue: store Wh + fused score reduction over tx (8 lanes)
    float awi[8], awj[8];
#pragma unroll
    for (int c = 0; c < 8; c++) {
        awi[c] = __ldg(&aw[tx * 8 + c]);
        awj[c] = __ldg(&aw[64 + tx * 8 + c]);
    }
#pragma unroll
    for (int r = 0; r < 8; r++) {
        int row = m0 + ty * 8 + r;
        float v[8];
#pragma unroll
        for (int c = 0; c < 4; c++) {
            v[2 * c]     = __uint_as_float((unsigned)(acc2[r][c] & 0xffffffffULL));
            v[2 * c + 1] = __uint_as_float((unsigned)(acc2[r][c] >> 32));
        }
        if (row < M) {
            *(float4*)&g_Wh[(size_t)row * NHID + tx * 8] =
                make_float4(v[0], v[1], v[2], v[3]);
            *(float4*)&g_Wh[(size_t)row * NHID + tx * 8 + 4] =
                make_float4(v[4], v[5], v[6], v[7]);
        }
        float si = 0.f, sj = 0.f;
#pragma unroll
        for (int c = 0; c < 8; c++) { si += v[c] * awi[c]; sj += v[c] * awj[c]; }
#pragma unroll
        for (int o = 4; o >= 1; o >>= 1) {
            si += __shfl_xor_sync(0xffffffffu, si, o);
            sj += __shfl_xor_sync(0xffffffffu, sj, o);
        }
        if (tx == 0 && row < M) { g_si[row] = si; g_sj[row] = sj; }
    }
}

// ---------------- exclusive scan over g_count (3 kernels) ----------------
__global__ void scan1_kernel(int M) {
    __shared__ int sm[256];
    int tid = threadIdx.x;
    int i = blockIdx.x * 256 + tid;
    int c = (i < M) ? g_count[i] : 0;
    sm[tid] = c;
    __syncthreads();
#pragma unroll
    for (int off = 1; off < 256; off <<= 1) {
        int v = (tid >= off) ? sm[tid - off] : 0;
        __syncthreads();
        sm[tid] += v;
        __syncthreads();
    }
    if (i < M) g_start[i] = sm[tid] - c;
    if (tid == 255) g_bsum[blockIdx.x] = sm[255];
}

__global__ void scan2_kernel(int nb) {
    __shared__ int sm[512];
    int tid = threadIdx.x;
    int c = (tid < nb) ? g_bsum[tid] : 0;
    sm[tid] = c;
    __syncthreads();
#pragma unroll
    for (int off = 1; off < 512; off <<= 1) {
        int v = (tid >= off) ? sm[tid - off] : 0;
        __syncthreads();
        sm[tid] += v;
        __syncthreads();
    }
    g_boff[tid] = sm[tid] - c;
}

__global__ void scan3_kernel(int M, int E) {
    int i = blockIdx.x * 256 + threadIdx.x;
    if (i >= M) return;
    int v = g_start[i] + g_boff[blockIdx.x];
    g_start[i] = v;
    g_cursor[i] = v;
    if (i == M - 1) g_start[M] = E;
}

// ---------------- edge pass A: h + hsum + sorted pack write ----------------
__global__ void edgeA_fused_kernel(const void* __restrict__ ei,
                                   const float* __restrict__ ab, int E, int M) {
    int e = blockIdx.x * blockDim.x + threadIdx.x;
    if (e >= E) return;
    const int is64 = g_idx64;
    int s = load_idx(ei, e, is64, M);
    int d = load_idx(ei, (size_t)E + e, is64, M);
    float sc = g_si[s] + g_sj[d] + __ldg(&ab[0]);
    float l  = sc > 0.f ? sc : NEG_SLOPE * sc;
    float h  = expf(l);
    g_h[e] = h;
    atomicAdd(&g_hsum[s], h);
    int pos = atomicAdd(&g_cursor[s], 1);
    g_pack[pos] = make_float2(h, __int_as_float(d));
}

// ---------------- reciprocal of h_sum ----------------
__global__ void recip_kernel(int M) {
    int n = blockIdx.x * blockDim.x + threadIdx.x;
    if (n >= M) return;
    g_hsum[n] = __frcp_rn(g_hsum[n]);
}

// ---------------- alpha in original edge order (fully coalesced) --------
__global__ void alpha_kernel(const void* __restrict__ ei,
                             float* __restrict__ alpha_out, int E, int M) {
    int e = blockIdx.x * blockDim.x + threadIdx.x;
    if (e >= E) return;
    int s = load_idx(ei, e, g_idx64, M);
    alpha_out[e] = g_h[e] * g_hsum[s];
}

// ---------------- edge pass B: CSR gather, warp per node ----------------
__global__ void __launch_bounds__(256) edgeB_csr_kernel(
        float* __restrict__ out, int M) {
    int warp = (blockIdx.x * blockDim.x + threadIdx.x) >> 5;
    if (warp >= M) return;
    int lane = threadIdx.x & 31;
    int sub  = lane >> 4;
    int part = lane & 15;

    int start = g_start[warp];
    int end   = g_start[warp + 1];
    float rinv = g_hsum[warp];

    float4 acc = make_float4(0.f, 0.f, 0.f, 0.f);
    for (int pos = start + sub; pos < end; pos += 2) {
        float2 p    = g_pack[pos];
        int    d    = __float_as_int(p.y);
        float alpha = p.x * rinv;
        float4 w = *(const float4*)&g_Wh[(size_t)d * NHID + part * 4];
        acc.x += alpha * w.x;
        acc.y += alpha * w.y;
        acc.z += alpha * w.z;
        acc.w += alpha * w.w;
    }
    acc.x += __shfl_down_sync(0xffffffffu, acc.x, 16);
    acc.y += __shfl_down_sync(0xffffffffu, acc.y, 16);
    acc.z += __shfl_down_sync(0xffffffffu, acc.z, 16);
    acc.w += __shfl_down_sync(0xffffffffu, acc.w, 16);
    if (sub == 0)
        *(float4*)&out[(size_t)warp * NHID + part * 4] = acc;
}

// ---------------- launch ----------------
extern "C" void kernel_launch(void* const* d_in, const int* in_sizes, int n_in,
                              void* d_out, int out_size) {
    const float* x  = (const float*)d_in[0];
    const float* W  = (const float*)d_in[1];
    const float* aw = (const float*)d_in[2];
    const float* ab = (const float*)d_in[3];
    const void*  ei = d_in[4];

    const int M = in_sizes[0] / NFEAT;       // 100000
    const int E = in_sizes[4] / 2;           // 1600000

    float* out       = (float*)d_out;                    // [M, 64]
    float* alpha_out = (out_size >= M * NHID + E) ? out + (size_t)M * NHID : nullptr;

    const int nb = (M + 255) / 256;          // scan blocks (<=512)

    // order keeps gemm_kernel at launch index 3 (ncu captures index 3)
    detect_kernel<<<1, 256>>>(ei, E, M);                       // 0
    zero_small_kernel<<<nb, 256>>>(M);                         // 1
    hist_kernel<<<(E + 255) / 256, 256>>>(ei, E, M);           // 2
    gemm_kernel<<<(M + BM - 1) / BM, 256>>>(x, W, aw, M);      // 3  <- profiled
    scan1_kernel<<<nb, 256>>>(M);                              // 4
    scan2_kernel<<<1, 512>>>(nb);                              // 5
    scan3_kernel<<<nb, 256>>>(M, E);                           // 6
    edgeA_fused_kernel<<<(E + 255) / 256, 256>>>(ei, ab, E, M);// 7
    recip_kernel<<<nb, 256>>>(M);                              // 8
    if (alpha_out)
        alpha_kernel<<<(E + 255) / 256, 256>>>(ei, alpha_out, E, M); // 9
    edgeB_csr_kernel<<<(M * 32 + 255) / 256, 256>>>(out, M);   // 10
}

// round 12
// speedup vs baseline: 1.2196x; 1.0142x over previous
#include <cuda_runtime.h>
#include <cstdint>

#define NFEAT 256
#define NHID 64
#define NEG_SLOPE 0.05f
#define MAX_N 100000
#define MAX_E 1600000
#define BM 256
#define BK 16
#define NTILE (NFEAT / BK)

// ---------------- device scratch (no allocation allowed) ----------------
__device__ float  g_Wh[(size_t)MAX_N * NHID];   // 25.6 MB
__device__ float  g_si[MAX_N];
__device__ float  g_sj[MAX_N];
__device__ float  g_hsum[MAX_N];                // written by edgeB: 1/sum(h)
__device__ float  g_h[MAX_E];                   // h in ORIGINAL edge order
__device__ int    g_idx64;
__device__ int    g_count[MAX_N];
__device__ int    g_start[MAX_N + 1];
__device__ int    g_cursor[MAX_N];
__device__ int    g_bsum[512];
__device__ int    g_boff[512];
__device__ float2 g_pack[MAX_E];                // {h, dst-as-bits} src-sorted

// ---------------- index helper: dtype-adaptive, clamped ----------------
__device__ __forceinline__ int load_idx(const void* ei, size_t pos, int is64, int M) {
    int v;
    if (is64) v = (int)((const long long*)ei)[pos];
    else      v = ((const int*)ei)[pos];
    v = v < 0 ? 0 : (v >= M ? M - 1 : v);
    return v;
}

// ---------------- detect edge_index dtype ----------------
__global__ void detect_kernel(const void* ei, int E, int M) {
    __shared__ int bad;
    if (threadIdx.x == 0) bad = 0;
    __syncthreads();
    const long long* p = (const long long*)ei;
    int stride = E / 4096 > 0 ? E / 4096 : 1;
    for (int i = threadIdx.x; i < 4096; i += blockDim.x) {
        size_t pos = (size_t)i * stride;
        if (pos < (size_t)E) {
            long long v = p[pos];
            if (v < 0 || v >= M) atomicOr(&bad, 1);
        }
    }
    __syncthreads();
    if (threadIdx.x == 0) g_idx64 = bad ? 0 : 1;
}

// ---------------- zero per-node edge counters ----------------
__global__ void zero_small_kernel(int M) {
    int i = blockIdx.x * blockDim.x + threadIdx.x;
    if (i < M) g_count[i] = 0;
}

// ---------------- histogram of src ----------------
__global__ void hist_kernel(const void* __restrict__ ei, int E, int M) {
    int e = blockIdx.x * blockDim.x + threadIdx.x;
    if (e >= E) return;
    int s = load_idx(ei, e, g_idx64, M);
    atomicAdd(&g_count[s], 1);
}

// ---------------- GEMM: Wh = x @ W_fc, FFMA2, double-buffered ----------
// BM=256, BN=64, BK=16, 256 threads, 8x8 microtile per thread.
__global__ void __launch_bounds__(256, 2) gemm_kernel(
        const float* __restrict__ x,
        const float* __restrict__ W,
        const float* __restrict__ aw,
        int M) {
    __shared__ float As[2][BK][BM];
    __shared__ float Bs[2][BK][NHID];

    const int tid = threadIdx.x;
    const int tx  = tid & 7;
    const int ty  = tid >> 3;
    const int m0  = blockIdx.x * BM;

    int arow[4], akc[4], aval[4];
    const float* aptr[4];
#pragma unroll
    for (int p = 0; p < 4; p++) {
        int idx = p * 256 + tid;
        arow[p] = idx >> 2;
        akc[p]  = (idx & 3) * 4;
        int gm  = m0 + arow[p];
        aval[p] = gm < M;
        aptr[p] = x + (size_t)(aval[p] ? gm : 0) * NFEAT + akc[p];
    }
    const int bk = tid >> 4, bj = (tid & 15) * 4;
    const float* bptr = W + (size_t)bk * NHID + bj;

    float4 astg[4], bstg;
#pragma unroll
    for (int p = 0; p < 4; p++)
        astg[p] = aval[p] ? *(const float4*)aptr[p]
                          : make_float4(0.f, 0.f, 0.f, 0.f);
    bstg = *(const float4*)bptr;

#pragma unroll
    for (int p = 0; p < 4; p++) {
        As[0][akc[p] + 0][arow[p]] = astg[p].x;
        As[0][akc[p] + 1][arow[p]] = astg[p].y;
        As[0][akc[p] + 2][arow[p]] = astg[p].z;
        As[0][akc[p] + 3][arow[p]] = astg[p].w;
    }
    *(float4*)&Bs[0][bk][bj] = bstg;
    __syncthreads();

    unsigned long long acc2[8][4];
#pragma unroll
    for (int r = 0; r < 8; r++)
#pragma unroll
        for (int c = 0; c < 4; c++) acc2[r][c] = 0ULL;

#pragma unroll 2
    for (int t = 0; t < NTILE; t++) {
        const int buf = t & 1;
        if (t + 1 < NTILE) {
#pragma unroll
            for (int p = 0; p < 4; p++)
                astg[p] = aval[p] ? *(const float4*)(aptr[p] + (t + 1) * BK)
                                  : make_float4(0.f, 0.f, 0.f, 0.f);
            bstg = *(const float4*)(bptr + (size_t)(t + 1) * BK * NHID);
        }
#pragma unroll
        for (int k = 0; k < BK; k++) {
            float4 aL = *(const float4*)&As[buf][k][ty * 8];
            float4 aH = *(const float4*)&As[buf][k][ty * 8 + 4];
            ulonglong2 bL = *(const ulonglong2*)&Bs[buf][k][tx * 8];
            ulonglong2 bH = *(const ulonglong2*)&Bs[buf][k][tx * 8 + 4];
            unsigned long long bp[4] = {bL.x, bL.y, bH.x, bH.y};
            unsigned avu[8] = {
                __float_as_uint(aL.x), __float_as_uint(aL.y),
                __float_as_uint(aL.z), __float_as_uint(aL.w),
                __float_as_uint(aH.x), __float_as_uint(aH.y),
                __float_as_uint(aH.z), __float_as_uint(aH.w)};
            unsigned long long ap[8];
#pragma unroll
            for (int r = 0; r < 8; r++)
                asm("mov.b64 %0, {%1, %1};" : "=l"(ap[r]) : "r"(avu[r]));
#pragma unroll
            for (int r = 0; r < 8; r++)
#pragma unroll
                for (int c = 0; c < 4; c++)
                    asm("fma.rn.f32x2 %0, %1, %2, %0;"
                        : "+l"(acc2[r][c]) : "l"(ap[r]), "l"(bp[c]));
        }
        if (t + 1 < NTILE) {
            const int nb = buf ^ 1;
#pragma unroll
            for (int p = 0; p < 4; p++) {
                As[nb][akc[p] + 0][arow[p]] = astg[p].x;
                As[nb][akc[p] + 1][arow[p]] = astg[p].y;
                As[nb][akc[p] + 2][arow[p]] = astg[p].z;
                As[nb][akc[p] + 3][arow[p]] = astg[p].w;
            }
            *(float4*)&Bs[nb][bk][bj] = bstg;
            __syncthreads();
        }
    }

    float awi[8], awj[8];
#pragma unroll
    for (int c = 0; c < 8; c++) {
        awi[c] = __ldg(&aw[tx * 8 + c]);
        awj[c] = __ldg(&aw[64 + tx * 8 + c]);
    }
#pragma unroll
    for (int r = 0; r < 8; r++) {
        int row = m0 + ty * 8 + r;
        float v[8];
#pragma unroll
        for (int c = 0; c < 4; c++) {
            v[2 * c]     = __uint_as_float((unsigned)(acc2[r][c] & 0xffffffffULL));
            v[2 * c + 1] = __uint_as_float((unsigned)(acc2[r][c] >> 32));
        }
        if (row < M) {
            *(float4*)&g_Wh[(size_t)row * NHID + tx * 8] =
                make_float4(v[0], v[1], v[2], v[3]);
            *(float4*)&g_Wh[(size_t)row * NHID + tx * 8 + 4] =
                make_float4(v[4], v[5], v[6], v[7]);
        }
        float si = 0.f, sj = 0.f;
#pragma unroll
        for (int c = 0; c < 8; c++) { si += v[c] * awi[c]; sj += v[c] * awj[c]; }
#pragma unroll
        for (int o = 4; o >= 1; o >>= 1) {
            si += __shfl_xor_sync(0xffffffffu, si, o);
            sj += __shfl_xor_sync(0xffffffffu, sj, o);
        }
        if (tx == 0 && row < M) { g_si[row] = si; g_sj[row] = sj; }
    }
}

// ---------------- exclusive scan over g_count (3 kernels) ----------------
__global__ void scan1_kernel(int M) {
    __shared__ int sm[256];
    int tid = threadIdx.x;
    int i = blockIdx.x * 256 + tid;
    int c = (i < M) ? g_count[i] : 0;
    sm[tid] = c;
    __syncthreads();
#pragma unroll
    for (int off = 1; off < 256; off <<= 1) {
        int v = (tid >= off) ? sm[tid - off] : 0;
        __syncthreads();
        sm[tid] += v;
        __syncthreads();
    }
    if (i < M) g_start[i] = sm[tid] - c;
    if (tid == 255) g_bsum[blockIdx.x] = sm[255];
}

__global__ void scan2_kernel(int nb) {
    __shared__ int sm[512];
    int tid = threadIdx.x;
    int c = (tid < nb) ? g_bsum[tid] : 0;
    sm[tid] = c;
    __syncthreads();
#pragma unroll
    for (int off = 1; off < 512; off <<= 1) {
        int v = (tid >= off) ? sm[tid - off] : 0;
        __syncthreads();
        sm[tid] += v;
        __syncthreads();
    }
    g_boff[tid] = sm[tid] - c;
}

__global__ void scan3_kernel(int M, int E) {
    int i = blockIdx.x * 256 + threadIdx.x;
    if (i >= M) return;
    int v = g_start[i] + g_boff[blockIdx.x];
    g_start[i] = v;
    g_cursor[i] = v;
    if (i == M - 1) g_start[M] = E;
}

// ---------------- edge pass A: h + sorted pack (NO hsum atomic) ---------
__global__ void edgeA_fused_kernel(const void* __restrict__ ei,
                                   const float* __restrict__ ab, int E, int M) {
    int e = blockIdx.x * blockDim.x + threadIdx.x;
    if (e >= E) return;
    const int is64 = g_idx64;
    int s = load_idx(ei, e, is64, M);
    int d = load_idx(ei, (size_t)E + e, is64, M);
    float sc = g_si[s] + g_sj[d] + __ldg(&ab[0]);
    float l  = sc > 0.f ? sc : NEG_SLOPE * sc;
    float h  = expf(l);
    g_h[e] = h;
    int pos = atomicAdd(&g_cursor[s], 1);
    g_pack[pos] = make_float2(h, __int_as_float(d));
}

// ---------------- edge pass B: CSR gather; h_sum folded in ----------------
// out[i] = (sum h*Wh[dst]) / (sum h); writes rinv to g_hsum for alpha pass.
__global__ void __launch_bounds__(256) edgeB_csr_kernel(
        float* __restrict__ out, int M) {
    int warp = (blockIdx.x * blockDim.x + threadIdx.x) >> 5;
    if (warp >= M) return;
    int lane = threadIdx.x & 31;
    int sub  = lane >> 4;
    int part = lane & 15;

    int start = g_start[warp];
    int end   = g_start[warp + 1];

    float4 acc = make_float4(0.f, 0.f, 0.f, 0.f);
    float  hs  = 0.f;                      // identical across 16 lanes of a sub
    for (int pos = start + sub; pos < end; pos += 2) {
        float2 p = g_pack[pos];
        int    d = __float_as_int(p.y);
        float  h = p.x;
        hs += h;
        float4 w = *(const float4*)&g_Wh[(size_t)d * NHID + part * 4];
        acc.x += h * w.x;
        acc.y += h * w.y;
        acc.z += h * w.z;
        acc.w += h * w.w;
    }
    acc.x += __shfl_down_sync(0xffffffffu, acc.x, 16);
    acc.y += __shfl_down_sync(0xffffffffu, acc.y, 16);
    acc.z += __shfl_down_sync(0xffffffffu, acc.z, 16);
    acc.w += __shfl_down_sync(0xffffffffu, acc.w, 16);
    hs    += __shfl_down_sync(0xffffffffu, hs,    16);
    if (sub == 0) {
        float rinv = hs > 0.f ? __frcp_rn(hs) : 0.f;
        *(float4*)&out[(size_t)warp * NHID + part * 4] =
            make_float4(acc.x * rinv, acc.y * rinv, acc.z * rinv, acc.w * rinv);
        if (part == 0) g_hsum[warp] = rinv;
    }
}

// ---------------- alpha in original edge order (after edgeB) ------------
__global__ void alpha_kernel(const void* __restrict__ ei,
                             float* __restrict__ alpha_out, int E, int M) {
    int e = blockIdx.x * blockDim.x + threadIdx.x;
    if (e >= E) return;
    int s = load_idx(ei, e, g_idx64, M);
    alpha_out[e] = g_h[e] * g_hsum[s];
}

// ---------------- launch ----------------
extern "C" void kernel_launch(void* const* d_in, const int* in_sizes, int n_in,
                              void* d_out, int out_size) {
    const float* x  = (const float*)d_in[0];
    const float* W  = (const float*)d_in[1];
    const float* aw = (const float*)d_in[2];
    const float* ab = (const float*)d_in[3];
    const void*  ei = d_in[4];

    const int M = in_sizes[0] / NFEAT;       // 100000
    const int E = in_sizes[4] / 2;           // 1600000

    float* out       = (float*)d_out;
    float* alpha_out = (out_size >= M * NHID + E) ? out + (size_t)M * NHID : nullptr;

    const int nb = (M + 255) / 256;          // scan blocks (<=512)

    // gemm stays at launch index 3 (ncu captures index 3)
    detect_kernel<<<1, 256>>>(ei, E, M);                          // 0
    zero_small_kernel<<<nb, 256>>>(M);                            // 1
    hist_kernel<<<(E + 255) / 256, 256>>>(ei, E, M);              // 2
    gemm_kernel<<<(M + BM - 1) / BM, 256>>>(x, W, aw, M);         // 3 <- profiled
    scan1_kernel<<<nb, 256>>>(M);                                 // 4
    scan2_kernel<<<1, 512>>>(nb);                                 // 5
    scan3_kernel<<<nb, 256>>>(M, E);                              // 6
    edgeA_fused_kernel<<<(E + 255) / 256, 256>>>(ei, ab, E, M);   // 7
    edgeB_csr_kernel<<<(M * 32 + 255) / 256, 256>>>(out, M);      // 8
    if (alpha_out)
        alpha_kernel<<<(E + 255) / 256, 256>>>(ei, alpha_out, E, M); // 9
}